// round 9
// baseline (speedup 1.0000x reference)
#include <cuda_runtime.h>
#include <cstdint>

#define BB    2048
#define TSEQ  512
#define HH    51
#define TTOT  544      // TSEQ + 32 future
#define NCTA  152      // one CTA per SM on GB300
#define NBIG  72       // first 72 CTAs take 14 elements, remaining 80 take 13
#define EPCMX 15       // padded elements per CTA (3 groups x 5)
#define NTHR  384      // 3 groups x 64 j x 2 gate-split
#define MPT   5        // elements per thread
#define WROW  232      // floats per j-row (208 used; 232 % 32 == 8 => conflict-free)
#define HROW  56       // floats per element row in h arrays

#define W_SZ   (51 * WROW)      // 11832 floats per weight matrix
#define XS_SZ  (EPCMX * TSEQ)   // 7680
#define HD_SZ  (EPCMX * HROW)   // 840
#define SM_FLOATS (3*W_SZ + XS_SZ + 2*HD_SZ + 256 + 256 + 256 + 64 + 32)
#define SM_BYTES  (SM_FLOATS * 4)

// ---------------- packed f32x2 helpers ----------------
__device__ __forceinline__ unsigned long long ffma2(unsigned long long a,
                                                    unsigned long long b,
                                                    unsigned long long c) {
    unsigned long long d;
    asm("fma.rn.f32x2 %0, %1, %2, %3;" : "=l"(d) : "l"(a), "l"(b), "l"(c));
    return d;
}
__device__ __forceinline__ float2 unpack2(unsigned long long v) {
    float2 r;
    asm("mov.b64 {%0, %1}, %2;" : "=f"(r.x), "=f"(r.y) : "l"(v));
    return r;
}
__device__ __forceinline__ float sigf(float x) {
    return __fdividef(1.0f, 1.0f + __expf(-x));
}
__device__ __forceinline__ float tanhf_fast(float x) {
    return __fdividef(2.0f, 1.0f + __expf(-2.0f * x)) - 1.0f;
}

// single matvec: acc{A,B}[m] += W[j, gates(2gs,2gs+1), :] . h[e0+m, :]
__device__ __forceinline__ void matvec_acc(const float* __restrict__ Wrow,
                                           const float* __restrict__ hbase,
                                           unsigned long long aA[MPT],
                                           unsigned long long aB[MPT]) {
#pragma unroll
    for (int q = 0; q < 13; q++) {
        ulonglong2 wa = *(const ulonglong2*)(Wrow + q * 16);
        ulonglong2 wb = *(const ulonglong2*)(Wrow + q * 16 + 8);
#pragma unroll
        for (int m = 0; m < MPT; m++) {
            ulonglong2 hp = *(const ulonglong2*)(hbase + m * HROW + q * 4);
            aA[m] = ffma2(wa.x, hp.x, aA[m]);
            aB[m] = ffma2(wa.y, hp.x, aB[m]);
            aA[m] = ffma2(wb.x, hp.y, aA[m]);
            aB[m] = ffma2(wb.y, hp.y, aB[m]);
        }
    }
}

// fused dual matvec: mv1 over h1_old and mv2h over h2_old, interleaved for ILP
__device__ __forceinline__ void matvec_dual(const float* __restrict__ Wr1,
                                            const float* __restrict__ Wr2,
                                            const float* __restrict__ h1,
                                            const float* __restrict__ h2,
                                            unsigned long long aA[MPT],
                                            unsigned long long aB[MPT],
                                            unsigned long long aC[MPT],
                                            unsigned long long aD[MPT]) {
#pragma unroll
    for (int q = 0; q < 13; q++) {
        ulonglong2 wa1 = *(const ulonglong2*)(Wr1 + q * 16);
        ulonglong2 wb1 = *(const ulonglong2*)(Wr1 + q * 16 + 8);
        ulonglong2 wa2 = *(const ulonglong2*)(Wr2 + q * 16);
        ulonglong2 wb2 = *(const ulonglong2*)(Wr2 + q * 16 + 8);
#pragma unroll
        for (int m = 0; m < MPT; m++) {
            ulonglong2 hp1 = *(const ulonglong2*)(h1 + m * HROW + q * 4);
            ulonglong2 hp2 = *(const ulonglong2*)(h2 + m * HROW + q * 4);
            aA[m] = ffma2(wa1.x, hp1.x, aA[m]);
            aB[m] = ffma2(wa1.y, hp1.x, aB[m]);
            aC[m] = ffma2(wa2.x, hp2.x, aC[m]);
            aD[m] = ffma2(wa2.y, hp2.x, aD[m]);
            aA[m] = ffma2(wb1.x, hp1.y, aA[m]);
            aB[m] = ffma2(wb1.y, hp1.y, aB[m]);
            aC[m] = ffma2(wb2.x, hp2.y, aC[m]);
            aD[m] = ffma2(wb2.y, hp2.y, aD[m]);
        }
    }
}

__global__ void __launch_bounds__(NTHR, 1)
lstm_seq_kernel(const float* __restrict__ input,
                const float* __restrict__ Wih1, const float* __restrict__ Whh1,
                const float* __restrict__ bih1, const float* __restrict__ bhh1,
                const float* __restrict__ Wih2, const float* __restrict__ Whh2,
                const float* __restrict__ bih2, const float* __restrict__ bhh2,
                const float* __restrict__ Wlin, const float* __restrict__ blin,
                float* __restrict__ out) {
    extern __shared__ float sm[];
    float* W1    = sm;
    float* W2i   = W1  + W_SZ;
    float* W2h   = W2i + W_SZ;
    float* xs    = W2h + W_SZ;         // [15][512]
    float* hd1   = xs  + XS_SZ;        // [15][56]
    float* hd2   = hd1 + HD_SZ;        // [15][56]
    float* wih1q = hd2 + HD_SZ;        // [64][4]
    float* b1q   = wih1q + 256;
    float* b2q   = b1q   + 256;
    float* wlin  = b2q   + 256;        // [64]
    float* outb  = wlin  + 64;         // [2][16] double-buffered

    const int tid = threadIdx.x;
    const int g   = tid >> 7;            // group 0..2 (5 elements each)
    const int r   = tid & 127;
    const int j   = r >> 1;
    const int gs  = r & 1;
    const int jj  = (j < HH) ? j : (HH - 1);
    const int cta = blockIdx.x;
    const int big = (cta < NBIG);
    const int epc = big ? 14 : 13;
    const int b0  = big ? cta * 14 : NBIG * 14 + (cta - NBIG) * 13;
    const int e0  = g * MPT;

    const float kmul = gs ? -2.0f : -1.0f;
    const float kA   = gs ?  2.0f :  1.0f;
    const float kB   = gs ? -1.0f :  0.0f;

    // ---------- one-time init ----------
    for (int idx = tid; idx < 51 * 26; idx += NTHR) {
        int jr = idx / 26;
        int kb = idx - jr * 26;
#pragma unroll
        for (int gg = 0; gg < 4; gg++) {
#pragma unroll
            for (int s = 0; s < 2; s++) {
                int k = 2 * kb + s;
                int rr = gg * 51 + jr;
                bool ok = (k < HH);
                int o = jr * WROW + kb * 8 + gg * 2 + s;
                W1 [o] = ok ? Whh1[rr * 51 + k] : 0.f;
                W2i[o] = ok ? Wih2[rr * 51 + k] : 0.f;
                W2h[o] = ok ? Whh2[rr * 51 + k] : 0.f;
            }
        }
    }
    if (tid < 64) {
#pragma unroll
        for (int gg = 0; gg < 4; gg++) {
            bool ok = tid < HH;
            wih1q[tid * 4 + gg] = ok ? Wih1[gg * 51 + tid] : 0.f;
            b1q  [tid * 4 + gg] = ok ? (bih1[gg * 51 + tid] + bhh1[gg * 51 + tid]) : 0.f;
            b2q  [tid * 4 + gg] = ok ? (bih2[gg * 51 + tid] + bhh2[gg * 51 + tid]) : 0.f;
        }
        wlin[tid] = (tid < HH) ? Wlin[tid] : 0.f;
    }
    for (int idx = tid; idx < XS_SZ; idx += NTHR) {
        int e = idx >> 9, tc = idx & 511;
        xs[idx] = (e < epc) ? input[(size_t)(b0 + e) * TSEQ + tc] : 0.f;
    }
    for (int idx = tid; idx < 2 * HD_SZ; idx += NTHR) hd1[idx] = 0.f;
    const float blin_r = blin[0];
    if (tid < 32) outb[tid] = blin_r;
    __syncthreads();

    float c1[MPT], c2[MPT];
#pragma unroll
    for (int m = 0; m < MPT; m++) { c1[m] = 0.f; c2[m] = 0.f; }

    const float*  W1r  = W1  + jj * WROW + gs * 4;
    const float*  W2ir = W2i + jj * WROW + gs * 4;
    const float*  W2hr = W2h + jj * WROW + gs * 4;
    const float2  wxp  = *(const float2*)(wih1q + jj * 4 + gs * 2);
    const float2  bp1  = *(const float2*)(b1q   + jj * 4 + gs * 2);
    const float2  bp2  = *(const float2*)(b2q   + jj * 4 + gs * 2);
    const float   wl   = (gs == 0) ? wlin[j] : 0.f;
    const float*  hd1g = hd1 + e0 * HROW;
    const float*  hd2g = hd2 + e0 * HROW;

    // ---------- sequential scan, 3 barriers/step ----------
    for (int t = 0; t < TTOT; t++) {
        float* outC = outb + ((t + 1) & 1) * 16;          // buffer holding out(t-1)
        float* outP = outb + (t & 1) * 16;                // buffer for out(t)

        // ---- phase 1: mv1 (old hd1) + mv2h (old hd2), fused ----
        unsigned long long aA[MPT], aB[MPT], aC[MPT], aD[MPT];
#pragma unroll
        for (int m = 0; m < MPT; m++) { aA[m] = 0; aB[m] = 0; aC[m] = 0; aD[m] = 0; }
        matvec_dual(W1r, W2hr, hd1g, hd2g, aA, aB, aC, aD);

        float z2A[MPT], z2B[MPT];                         // compress mv2h partials
#pragma unroll
        for (int m = 0; m < MPT; m++) {
            float2 vc = unpack2(aC[m]); z2A[m] = vc.x + vc.y;
            float2 vd = unpack2(aD[m]); z2B[m] = vd.x + vd.y;
        }
        __syncthreads();                                  // S_a: old-state reads done; outC complete

        // out(t-1) write + feedback/teacher x read
        if (t >= 1 && tid < epc)
            out[(size_t)(b0 + tid) * TTOT + (t - 1)] = outC[tid];
        float xm[MPT];
        if (t < TSEQ) {
#pragma unroll
            for (int m = 0; m < MPT; m++) xm[m] = xs[(e0 + m) * TSEQ + t];
        } else {
#pragma unroll
            for (int m = 0; m < MPT; m++) xm[m] = outC[e0 + m];
        }

        // ---- L1 combine -> new hd1 ----
        float h1n[MPT];
#pragma unroll
        for (int m = 0; m < MPT; m++) {
            float2 va = unpack2(aA[m]);
            float2 vb = unpack2(aB[m]);
            float za = va.x + va.y + fmaf(wxp.x, xm[m], bp1.x);
            float zb = vb.x + vb.y + fmaf(wxp.y, xm[m], bp1.y);
            float a1 = kA * __fdividef(1.0f, 1.0f + __expf(kmul * za)) + kB; // i|g
            float a2 = sigf(zb);                                             // f|o
            float g_r = __shfl_xor_sync(0xffffffffu, a1, 1);
            float o_r = __shfl_xor_sync(0xffffffffu, a2, 1);
            c1[m]  = a2 * c1[m] + a1 * g_r;
            h1n[m] = o_r * tanhf_fast(c1[m]);
        }
        if (gs == 0 && j < HH) {
#pragma unroll
            for (int m = 0; m < MPT; m++)
                hd1[(e0 + m) * HROW + j] = h1n[m];
        }
        __syncthreads();                                  // S_b: new hd1 visible; outC reads done

        if (tid < 16) outC[tid] = blin_r;                 // reset buffer for step t+1

        // ---- phase 2: mv2i over new hd1 ----
#pragma unroll
        for (int m = 0; m < MPT; m++) { aA[m] = 0; aB[m] = 0; }
        matvec_acc(W2ir, hd1g, aA, aB);

        // ---- L2 combine -> new hd2 + output ----
        float h2n[MPT];
#pragma unroll
        for (int m = 0; m < MPT; m++) {
            float2 va = unpack2(aA[m]);
            float2 vb = unpack2(aB[m]);
            float za = va.x + va.y + z2A[m] + bp2.x;
            float zb = vb.x + vb.y + z2B[m] + bp2.y;
            float a1 = kA * __fdividef(1.0f, 1.0f + __expf(kmul * za)) + kB;
            float a2 = sigf(zb);
            float g_r = __shfl_xor_sync(0xffffffffu, a1, 1);
            float o_r = __shfl_xor_sync(0xffffffffu, a2, 1);
            c2[m]  = a2 * c2[m] + a1 * g_r;
            h2n[m] = o_r * tanhf_fast(c2[m]);
        }
        if (gs == 0 && j < HH) {
#pragma unroll
            for (int m = 0; m < MPT; m++)
                hd2[(e0 + m) * HROW + j] = h2n[m];
        }
#pragma unroll
        for (int m = 0; m < MPT; m++) {
            float p = wl * h2n[m];
#pragma unroll
            for (int off = 16; off > 0; off >>= 1)
                p += __shfl_xor_sync(0xffffffffu, p, off);
            if ((tid & 31) == 0) atomicAdd(&outP[e0 + m], p);
        }
        __syncthreads();                                  // S_c: hd2 + outP atomics complete
    }
    // final output column: out(TTOT-1) lives in buffer (TTOT-1)&1
    if (tid < epc)
        out[(size_t)(b0 + tid) * TTOT + (TTOT - 1)] = outb[((TTOT - 1) & 1) * 16 + tid];
}

extern "C" void kernel_launch(void* const* d_in, const int* in_sizes, int n_in,
                              void* d_out, int out_size) {
    const float* input = (const float*)d_in[0];
    const float* Wih1  = (const float*)d_in[1];
    const float* Whh1  = (const float*)d_in[2];
    const float* bih1  = (const float*)d_in[3];
    const float* bhh1  = (const float*)d_in[4];
    const float* Wih2  = (const float*)d_in[5];
    const float* Whh2  = (const float*)d_in[6];
    const float* bih2  = (const float*)d_in[7];
    const float* bhh2  = (const float*)d_in[8];
    const float* Wlin  = (const float*)d_in[9];
    const float* blin  = (const float*)d_in[10];
    // d_in[11] = "future" (=32), baked in as a constant.

    cudaFuncSetAttribute(lstm_seq_kernel,
                         cudaFuncAttributeMaxDynamicSharedMemorySize, SM_BYTES);
    lstm_seq_kernel<<<NCTA, NTHR, SM_BYTES>>>(input, Wih1, Whh1, bih1, bhh1,
                                              Wih2, Whh2, bih2, bhh2,
                                              Wlin, blin, (float*)d_out);
}

// round 10
// speedup vs baseline: 1.0950x; 1.0950x over previous
#include <cuda_runtime.h>
#include <cstdint>

#define BB    2048
#define TSEQ  512
#define HH    51
#define TTOT  544      // TSEQ + 32 future
#define NCTA  152      // one CTA per SM on GB300
#define NBIG  72       // first 72 CTAs take 14 elements, remaining 80 take 13
#define EPCMX 14
#define NTHR  256      // 2 groups x 64 j x 2 gate-split
#define MPT   7        // elements per thread
#define WROW  232      // floats per j-row (208 used; 232 % 32 == 8 => conflict-free)
#define HROW  56       // floats per element row in h arrays

#define W_SZ   (51 * WROW)      // 11832 floats per weight matrix
#define XS_SZ  (EPCMX * TSEQ)   // 7168
#define HDBUF  (EPCMX * HROW)   // 784 floats per h buffer
#define SM_FLOATS (3*W_SZ + XS_SZ + 4*HDBUF + 256 + 256 + 256 + 64 + 32)
#define SM_BYTES  (SM_FLOATS * 4)

#define BAR_GRP(gid) asm volatile("bar.sync %0, 128;" :: "r"(1 + (gid)) : "memory")

// ---------------- packed f32x2 helpers ----------------
__device__ __forceinline__ unsigned long long ffma2(unsigned long long a,
                                                    unsigned long long b,
                                                    unsigned long long c) {
    unsigned long long d;
    asm("fma.rn.f32x2 %0, %1, %2, %3;" : "=l"(d) : "l"(a), "l"(b), "l"(c));
    return d;
}
__device__ __forceinline__ float2 unpack2(unsigned long long v) {
    float2 r;
    asm("mov.b64 {%0, %1}, %2;" : "=f"(r.x), "=f"(r.y) : "l"(v));
    return r;
}
__device__ __forceinline__ float sigf(float x) {
    return __fdividef(1.0f, 1.0f + __expf(-x));
}
__device__ __forceinline__ float tanhf_fast(float x) {
    return __fdividef(2.0f, 1.0f + __expf(-2.0f * x)) - 1.0f;
}

// single matvec: acc{A,B}[m] += W[j, gates(2gs,2gs+1), :] . h[e0+m, :]
__device__ __forceinline__ void matvec_acc(const float* __restrict__ Wrow,
                                           const float* __restrict__ hbase,
                                           unsigned long long aA[MPT],
                                           unsigned long long aB[MPT]) {
#pragma unroll
    for (int q = 0; q < 13; q++) {
        ulonglong2 wa = *(const ulonglong2*)(Wrow + q * 16);
        ulonglong2 wb = *(const ulonglong2*)(Wrow + q * 16 + 8);
#pragma unroll
        for (int m = 0; m < MPT; m++) {
            ulonglong2 hp = *(const ulonglong2*)(hbase + m * HROW + q * 4);
            aA[m] = ffma2(wa.x, hp.x, aA[m]);
            aB[m] = ffma2(wa.y, hp.x, aB[m]);
            aA[m] = ffma2(wb.x, hp.y, aA[m]);
            aB[m] = ffma2(wb.y, hp.y, aB[m]);
        }
    }
}

// fused dual matvec: mv1 over h1_old and mv2h over h2_old, interleaved for ILP
__device__ __forceinline__ void matvec_dual(const float* __restrict__ Wr1,
                                            const float* __restrict__ Wr2,
                                            const float* __restrict__ h1,
                                            const float* __restrict__ h2,
                                            unsigned long long aA[MPT],
                                            unsigned long long aB[MPT],
                                            unsigned long long aC[MPT],
                                            unsigned long long aD[MPT]) {
#pragma unroll
    for (int q = 0; q < 13; q++) {
        ulonglong2 wa1 = *(const ulonglong2*)(Wr1 + q * 16);
        ulonglong2 wb1 = *(const ulonglong2*)(Wr1 + q * 16 + 8);
        ulonglong2 wa2 = *(const ulonglong2*)(Wr2 + q * 16);
        ulonglong2 wb2 = *(const ulonglong2*)(Wr2 + q * 16 + 8);
#pragma unroll
        for (int m = 0; m < MPT; m++) {
            ulonglong2 hp1 = *(const ulonglong2*)(h1 + m * HROW + q * 4);
            ulonglong2 hp2 = *(const ulonglong2*)(h2 + m * HROW + q * 4);
            aA[m] = ffma2(wa1.x, hp1.x, aA[m]);
            aB[m] = ffma2(wa1.y, hp1.x, aB[m]);
            aC[m] = ffma2(wa2.x, hp2.x, aC[m]);
            aD[m] = ffma2(wa2.y, hp2.x, aD[m]);
            aA[m] = ffma2(wb1.x, hp1.y, aA[m]);
            aB[m] = ffma2(wb1.y, hp1.y, aB[m]);
            aC[m] = ffma2(wb2.x, hp2.y, aC[m]);
            aD[m] = ffma2(wb2.y, hp2.y, aD[m]);
        }
    }
}

__global__ void __launch_bounds__(NTHR, 1)
lstm_seq_kernel(const float* __restrict__ input,
                const float* __restrict__ Wih1, const float* __restrict__ Whh1,
                const float* __restrict__ bih1, const float* __restrict__ bhh1,
                const float* __restrict__ Wih2, const float* __restrict__ Whh2,
                const float* __restrict__ bih2, const float* __restrict__ bhh2,
                const float* __restrict__ Wlin, const float* __restrict__ blin,
                float* __restrict__ out) {
    extern __shared__ float sm[];
    float* W1    = sm;
    float* W2i   = W1  + W_SZ;
    float* W2h   = W2i + W_SZ;
    float* xs    = W2h + W_SZ;         // [14][512]
    float* hd1   = xs  + XS_SZ;        // [2][14][56] double-buffered h1
    float* hd2   = hd1 + 2 * HDBUF;    // [2][14][56] double-buffered h2
    float* wih1q = hd2 + 2 * HDBUF;    // [64][4]
    float* b1q   = wih1q + 256;
    float* b2q   = b1q   + 256;
    float* wlin  = b2q   + 256;        // [64]
    float* ov    = wlin  + 64;         // [2][16] double-buffered outputs

    const int tid = threadIdx.x;
    const int g   = tid >> 7;            // group 0..1 (7 elements each)
    const int r   = tid & 127;
    const int j   = r >> 1;
    const int gs  = r & 1;
    const int jj  = (j < HH) ? j : (HH - 1);
    const int cta = blockIdx.x;
    const int big = (cta < NBIG);
    const int epc = big ? 14 : 13;
    const int b0  = big ? cta * 14 : NBIG * 14 + (cta - NBIG) * 13;
    const int e0  = g * MPT;

    const float kmul = gs ? -2.0f : -1.0f;
    const float kA   = gs ?  2.0f :  1.0f;
    const float kB   = gs ? -1.0f :  0.0f;

    // ---------- one-time init (full-CTA) ----------
    for (int idx = tid; idx < 51 * 26; idx += NTHR) {
        int jr = idx / 26;
        int kb = idx - jr * 26;
#pragma unroll
        for (int gg = 0; gg < 4; gg++) {
#pragma unroll
            for (int s = 0; s < 2; s++) {
                int k = 2 * kb + s;
                int rr = gg * 51 + jr;
                bool ok = (k < HH);
                int o = jr * WROW + kb * 8 + gg * 2 + s;
                W1 [o] = ok ? Whh1[rr * 51 + k] : 0.f;
                W2i[o] = ok ? Wih2[rr * 51 + k] : 0.f;
                W2h[o] = ok ? Whh2[rr * 51 + k] : 0.f;
            }
        }
    }
    if (tid < 64) {
#pragma unroll
        for (int gg = 0; gg < 4; gg++) {
            bool ok = tid < HH;
            wih1q[tid * 4 + gg] = ok ? Wih1[gg * 51 + tid] : 0.f;
            b1q  [tid * 4 + gg] = ok ? (bih1[gg * 51 + tid] + bhh1[gg * 51 + tid]) : 0.f;
            b2q  [tid * 4 + gg] = ok ? (bih2[gg * 51 + tid] + bhh2[gg * 51 + tid]) : 0.f;
        }
        wlin[tid] = (tid < HH) ? Wlin[tid] : 0.f;
    }
    for (int idx = tid; idx < XS_SZ; idx += NTHR) {
        int e = idx >> 9, tc = idx & 511;
        xs[idx] = (e < epc) ? input[(size_t)(b0 + e) * TSEQ + tc] : 0.f;
    }
    for (int idx = tid; idx < 4 * HDBUF; idx += NTHR) hd1[idx] = 0.f;
    const float blin_r = blin[0];
    if (tid < 32) ov[tid] = blin_r;
    __syncthreads();

    float c1[MPT], c2[MPT];
#pragma unroll
    for (int m = 0; m < MPT; m++) { c1[m] = 0.f; c2[m] = 0.f; }

    const float*  W1r  = W1  + jj * WROW + gs * 4;
    const float*  W2ir = W2i + jj * WROW + gs * 4;
    const float*  W2hr = W2h + jj * WROW + gs * 4;
    const float2  wxp  = *(const float2*)(wih1q + jj * 4 + gs * 2);
    const float2  bp1  = *(const float2*)(b1q   + jj * 4 + gs * 2);
    const float2  bp2  = *(const float2*)(b2q   + jj * 4 + gs * 2);
    const float   wl   = (gs == 0) ? wlin[j] : 0.f;

    // ---------- sequential scan: 2 GROUP-LOCAL barriers per step ----------
    for (int t = 0; t < TTOT; t++) {
        const int p = t & 1;
        const float* h1r = hd1 + p * HDBUF + e0 * HROW;          // h1(t-1)
        const float* h2r = hd2 + p * HDBUF + e0 * HROW;          // h2(t-1)
        float* h1w = hd1 + (p ^ 1) * HDBUF;                      // h1(t)
        float* h2w = hd2 + (p ^ 1) * HDBUF;                      // h2(t)
        float* ovC = ov + ((t + 1) & 1) * 16;                    // holds out(t-1); becomes out(t+1) slot
        float* ovP = ov + p * 16;                                // out(t) accumulator

        // ---- phase 1: mv1 (h1 old) + mv2h (h2 old), fused ----
        unsigned long long aA[MPT], aB[MPT], aC[MPT], aD[MPT];
#pragma unroll
        for (int m = 0; m < MPT; m++) { aA[m] = 0; aB[m] = 0; aC[m] = 0; aD[m] = 0; }
        matvec_dual(W1r, W2hr, h1r, h2r, aA, aB, aC, aD);

        float z2A[MPT], z2B[MPT];                                // compress mv2h partials
#pragma unroll
        for (int m = 0; m < MPT; m++) {
            float2 vc = unpack2(aC[m]); z2A[m] = vc.x + vc.y;
            float2 vd = unpack2(aD[m]); z2B[m] = vd.x + vd.y;
        }

        // out(t-1) gmem write (group-local; finalized at BAR_B of step t-1)
        if (t >= 1 && r < MPT && (e0 + r) < epc)
            out[(size_t)(b0 + e0 + r) * TTOT + (t - 1)] = ovC[e0 + r];

        // x: teacher-forced from xs, else feedback out(t-1)
        float xm[MPT];
        if (t < TSEQ) {
#pragma unroll
            for (int m = 0; m < MPT; m++) xm[m] = xs[(e0 + m) * TSEQ + t];
        } else {
#pragma unroll
            for (int m = 0; m < MPT; m++) xm[m] = ovC[e0 + m];
        }

        // ---- L1 combine -> h1(t) into buffer p^1 ----
        float h1n[MPT];
#pragma unroll
        for (int m = 0; m < MPT; m++) {
            float2 va = unpack2(aA[m]);
            float2 vb = unpack2(aB[m]);
            float za = va.x + va.y + fmaf(wxp.x, xm[m], bp1.x);
            float zb = vb.x + vb.y + fmaf(wxp.y, xm[m], bp1.y);
            float a1 = kA * __fdividef(1.0f, 1.0f + __expf(kmul * za)) + kB; // i|g
            float a2 = sigf(zb);                                             // f|o
            float g_r = __shfl_xor_sync(0xffffffffu, a1, 1);
            float o_r = __shfl_xor_sync(0xffffffffu, a2, 1);
            c1[m]  = a2 * c1[m] + a1 * g_r;
            h1n[m] = o_r * tanhf_fast(c1[m]);
        }
        if (gs == 0 && j < HH) {
#pragma unroll
            for (int m = 0; m < MPT; m++)
                h1w[(e0 + m) * HROW + j] = h1n[m];
        }
        BAR_GRP(g);                                       // A: h1(t) visible; ovC reads done (group)

        // reset the slot that will accumulate out(t+1)
        if (r < MPT) ovC[e0 + r] = blin_r;

        // ---- phase 2: mv2i over h1(t) ----
#pragma unroll
        for (int m = 0; m < MPT; m++) { aA[m] = 0; aB[m] = 0; }
        matvec_acc(W2ir, h1w + e0 * HROW, aA, aB);

        // ---- L2 combine -> h2(t) + output ----
        float h2n[MPT];
#pragma unroll
        for (int m = 0; m < MPT; m++) {
            float2 va = unpack2(aA[m]);
            float2 vb = unpack2(aB[m]);
            float za = va.x + va.y + z2A[m] + bp2.x;
            float zb = vb.x + vb.y + z2B[m] + bp2.y;
            float a1 = kA * __fdividef(1.0f, 1.0f + __expf(kmul * za)) + kB;
            float a2 = sigf(zb);
            float g_r = __shfl_xor_sync(0xffffffffu, a1, 1);
            float o_r = __shfl_xor_sync(0xffffffffu, a2, 1);
            c2[m]  = a2 * c2[m] + a1 * g_r;
            h2n[m] = o_r * tanhf_fast(c2[m]);
        }
        if (gs == 0 && j < HH) {
#pragma unroll
            for (int m = 0; m < MPT; m++)
                h2w[(e0 + m) * HROW + j] = h2n[m];
        }
#pragma unroll
        for (int m = 0; m < MPT; m++) {
            float pp = wl * h2n[m];
#pragma unroll
            for (int off = 16; off > 0; off >>= 1)
                pp += __shfl_xor_sync(0xffffffffu, pp, off);
            if ((r & 31) == 0) atomicAdd(&ovP[e0 + m], pp);
        }
        BAR_GRP(g);                                       // B: h2(t) + out(t) atomics complete
    }
    // final output column
    if (r < MPT && (e0 + r) < epc)
        out[(size_t)(b0 + e0 + r) * TTOT + (TTOT - 1)] = ov[((TTOT - 1) & 1) * 16 + e0 + r];
}

extern "C" void kernel_launch(void* const* d_in, const int* in_sizes, int n_in,
                              void* d_out, int out_size) {
    const float* input = (const float*)d_in[0];
    const float* Wih1  = (const float*)d_in[1];
    const float* Whh1  = (const float*)d_in[2];
    const float* bih1  = (const float*)d_in[3];
    const float* bhh1  = (const float*)d_in[4];
    const float* Wih2  = (const float*)d_in[5];
    const float* Whh2  = (const float*)d_in[6];
    const float* bih2  = (const float*)d_in[7];
    const float* bhh2  = (const float*)d_in[8];
    const float* Wlin  = (const float*)d_in[9];
    const float* blin  = (const float*)d_in[10];
    // d_in[11] = "future" (=32), baked in as a constant.

    cudaFuncSetAttribute(lstm_seq_kernel,
                         cudaFuncAttributeMaxDynamicSharedMemorySize, SM_BYTES);
    lstm_seq_kernel<<<NCTA, NTHR, SM_BYTES>>>(input, Wih1, Whh1, bih1, bhh1,
                                              Wih2, Whh2, bih2, bhh2,
                                              Wlin, blin, (float*)d_out);
}

// round 11
// speedup vs baseline: 1.2310x; 1.1242x over previous
#include <cuda_runtime.h>
#include <cstdint>

#define BB    2048
#define TSEQ  512
#define HH    51
#define TTOT  544      // TSEQ + 32 future
#define NCTA  152      // one CTA per SM on GB300
#define NBIG  72       // first 72 CTAs take 14 elements, remaining 80 take 13
#define EPCMX 14
#define NTHR  256      // 2 groups x 64 j x 2 gate-split
#define MPT   7        // elements per thread
#define WROW  232      // floats per j-row (208 used; 232 % 32 == 8 => conflict-free)
#define HROW  56       // floats per element row in h arrays

#define W_SZ   (51 * WROW)      // 11832 floats per weight matrix
#define XS_SZ  (EPCMX * TSEQ)   // 7168
#define HD_SZ  (EPCMX * HROW)   // 784
#define SM_FLOATS (3*W_SZ + XS_SZ + 2*HD_SZ + 256 + 256 + 256 + 64 + 32)
#define SM_BYTES  (SM_FLOATS * 4)

// ---------------- packed f32x2 helpers ----------------
__device__ __forceinline__ unsigned long long ffma2(unsigned long long a,
                                                    unsigned long long b,
                                                    unsigned long long c) {
    unsigned long long d;
    asm("fma.rn.f32x2 %0, %1, %2, %3;" : "=l"(d) : "l"(a), "l"(b), "l"(c));
    return d;
}
__device__ __forceinline__ float2 unpack2(unsigned long long v) {
    float2 r;
    asm("mov.b64 {%0, %1}, %2;" : "=f"(r.x), "=f"(r.y) : "l"(v));
    return r;
}
__device__ __forceinline__ float sigf(float x) {
    return __fdividef(1.0f, 1.0f + __expf(-x));
}
__device__ __forceinline__ float tanhf_fast(float x) {
    return __fdividef(2.0f, 1.0f + __expf(-2.0f * x)) - 1.0f;
}

// single matvec: acc{A,B}[m] += W[j, gates(2gs,2gs+1), :] . h[e0+m, :]
__device__ __forceinline__ void matvec_acc(const float* __restrict__ Wrow,
                                           const float* __restrict__ hbase,
                                           unsigned long long aA[MPT],
                                           unsigned long long aB[MPT]) {
#pragma unroll
    for (int q = 0; q < 13; q++) {
        ulonglong2 wa = *(const ulonglong2*)(Wrow + q * 16);
        ulonglong2 wb = *(const ulonglong2*)(Wrow + q * 16 + 8);
#pragma unroll
        for (int m = 0; m < MPT; m++) {
            ulonglong2 hp = *(const ulonglong2*)(hbase + m * HROW + q * 4);
            aA[m] = ffma2(wa.x, hp.x, aA[m]);
            aB[m] = ffma2(wa.y, hp.x, aB[m]);
            aA[m] = ffma2(wb.x, hp.y, aA[m]);
            aB[m] = ffma2(wb.y, hp.y, aB[m]);
        }
    }
}

// shared-operand dual matvec: TWO weight matrices against the SAME h vector.
// hp is loaded ONCE per (q, m) and feeds both weight sets.
__device__ __forceinline__ void matvec_dual_sh(const float* __restrict__ Wr1,
                                               const float* __restrict__ Wr2,
                                               const float* __restrict__ h,
                                               unsigned long long aA[MPT],
                                               unsigned long long aB[MPT],
                                               unsigned long long aC[MPT],
                                               unsigned long long aD[MPT]) {
#pragma unroll
    for (int q = 0; q < 13; q++) {
        ulonglong2 wa1 = *(const ulonglong2*)(Wr1 + q * 16);
        ulonglong2 wb1 = *(const ulonglong2*)(Wr1 + q * 16 + 8);
        ulonglong2 wa2 = *(const ulonglong2*)(Wr2 + q * 16);
        ulonglong2 wb2 = *(const ulonglong2*)(Wr2 + q * 16 + 8);
#pragma unroll
        for (int m = 0; m < MPT; m++) {
            ulonglong2 hp = *(const ulonglong2*)(h + m * HROW + q * 4);
            aA[m] = ffma2(wa1.x, hp.x, aA[m]);
            aB[m] = ffma2(wa1.y, hp.x, aB[m]);
            aC[m] = ffma2(wa2.x, hp.x, aC[m]);
            aD[m] = ffma2(wa2.y, hp.x, aD[m]);
            aA[m] = ffma2(wb1.x, hp.y, aA[m]);
            aB[m] = ffma2(wb1.y, hp.y, aB[m]);
            aC[m] = ffma2(wb2.x, hp.y, aC[m]);
            aD[m] = ffma2(wb2.y, hp.y, aD[m]);
        }
    }
}

__global__ void __launch_bounds__(NTHR, 1)
lstm_seq_kernel(const float* __restrict__ input,
                const float* __restrict__ Wih1, const float* __restrict__ Whh1,
                const float* __restrict__ bih1, const float* __restrict__ bhh1,
                const float* __restrict__ Wih2, const float* __restrict__ Whh2,
                const float* __restrict__ bih2, const float* __restrict__ bhh2,
                const float* __restrict__ Wlin, const float* __restrict__ blin,
                float* __restrict__ out) {
    extern __shared__ float sm[];
    float* W1    = sm;
    float* W2i   = W1  + W_SZ;
    float* W2h   = W2i + W_SZ;
    float* xs    = W2h + W_SZ;         // [14][512]
    float* hd1   = xs  + XS_SZ;        // [14][56]  single-buffered h1
    float* hd2   = hd1 + HD_SZ;        // [14][56]  single-buffered h2
    float* wih1q = hd2 + HD_SZ;        // [64][4]
    float* b1q   = wih1q + 256;
    float* b2q   = b1q   + 256;
    float* wlin  = b2q   + 256;        // [64]
    float* ov    = wlin  + 64;         // [2][16] double-buffered outputs

    const int tid = threadIdx.x;
    const int g   = tid >> 7;
    const int r   = tid & 127;
    const int j   = r >> 1;
    const int gs  = r & 1;
    const int jj  = (j < HH) ? j : (HH - 1);
    const int cta = blockIdx.x;
    const int big = (cta < NBIG);
    const int epc = big ? 14 : 13;
    const int b0  = big ? cta * 14 : NBIG * 14 + (cta - NBIG) * 13;
    const int e0  = g * MPT;

    const float kmul = gs ? -2.0f : -1.0f;
    const float kA   = gs ?  2.0f :  1.0f;
    const float kB   = gs ? -1.0f :  0.0f;

    // ---------- one-time init ----------
    for (int idx = tid; idx < 51 * 26; idx += NTHR) {
        int jr = idx / 26;
        int kb = idx - jr * 26;
#pragma unroll
        for (int gg = 0; gg < 4; gg++) {
#pragma unroll
            for (int s = 0; s < 2; s++) {
                int k = 2 * kb + s;
                int rr = gg * 51 + jr;
                bool ok = (k < HH);
                int o = jr * WROW + kb * 8 + gg * 2 + s;
                W1 [o] = ok ? Whh1[rr * 51 + k] : 0.f;
                W2i[o] = ok ? Wih2[rr * 51 + k] : 0.f;
                W2h[o] = ok ? Whh2[rr * 51 + k] : 0.f;
            }
        }
    }
    if (tid < 64) {
#pragma unroll
        for (int gg = 0; gg < 4; gg++) {
            bool ok = tid < HH;
            wih1q[tid * 4 + gg] = ok ? Wih1[gg * 51 + tid] : 0.f;
            b1q  [tid * 4 + gg] = ok ? (bih1[gg * 51 + tid] + bhh1[gg * 51 + tid]) : 0.f;
            b2q  [tid * 4 + gg] = ok ? (bih2[gg * 51 + tid] + bhh2[gg * 51 + tid]) : 0.f;
        }
        wlin[tid] = (tid < HH) ? Wlin[tid] : 0.f;
    }
    for (int idx = tid; idx < XS_SZ; idx += NTHR) {
        int e = idx >> 9, tc = idx & 511;
        xs[idx] = (e < epc) ? input[(size_t)(b0 + e) * TSEQ + tc] : 0.f;
    }
    for (int idx = tid; idx < 2 * HD_SZ; idx += NTHR) hd1[idx] = 0.f;
    const float blin_r = blin[0];
    if (tid < 32) ov[tid] = blin_r;
    __syncthreads();

    float c1[MPT], c2[MPT], z2A[MPT], z2B[MPT];
#pragma unroll
    for (int m = 0; m < MPT; m++) { c1[m] = 0.f; c2[m] = 0.f; z2A[m] = 0.f; z2B[m] = 0.f; }

    const float*  W1r  = W1  + jj * WROW + gs * 4;
    const float*  W2ir = W2i + jj * WROW + gs * 4;
    const float*  W2hr = W2h + jj * WROW + gs * 4;
    const float2  wxp  = *(const float2*)(wih1q + jj * 4 + gs * 2);
    const float2  bp1  = *(const float2*)(b1q   + jj * 4 + gs * 2);
    const float2  bp2  = *(const float2*)(b2q   + jj * 4 + gs * 2);
    const float   wl   = (gs == 0) ? wlin[j] : 0.f;
    const float*  hd1g = hd1 + e0 * HROW;
    const float*  hd2g = hd2 + e0 * HROW;

    // ---------- prologue: h1(0) in closed form (h1(-1) = c1(-1) = 0) ----------
#pragma unroll
    for (int m = 0; m < MPT; m++) {
        float x0 = xs[(e0 + m) * TSEQ];
        float za = fmaf(wxp.x, x0, bp1.x);
        float zb = fmaf(wxp.y, x0, bp1.y);
        float a1 = kA * __fdividef(1.0f, 1.0f + __expf(kmul * za)) + kB; // i|g
        float a2 = sigf(zb);                                             // f|o
        float g_r = __shfl_xor_sync(0xffffffffu, a1, 1);
        float o_r = __shfl_xor_sync(0xffffffffu, a2, 1);
        c1[m] = a1 * g_r;                       // f * 0 + i * g
        float h1n = o_r * tanhf_fast(c1[m]);
        if (gs == 0 && j < HH)
            hd1[(e0 + m) * HROW + j] = h1n;
    }
    __syncthreads();                            // h1(0) visible

    // ---------- pipelined scan: iteration t emits h2(t), out(t), h1(t+1) ----------
    for (int t = 0; t < TTOT; t++) {
        float* ovP = ov + (t & 1) * 16;                   // out(t) accumulator
        float* ovN = ov + ((t + 1) & 1) * 16;             // out(t+1) slot (reset below)

        // ---- phase A: dual matvec over h1(t): {mv2i(t), mv1(t+1)} ----
        unsigned long long aA[MPT], aB[MPT], aC[MPT], aD[MPT];
#pragma unroll
        for (int m = 0; m < MPT; m++) { aA[m] = 0; aB[m] = 0; aC[m] = 0; aD[m] = 0; }
        matvec_dual_sh(W2ir, W1r, hd1g, aA, aB, aC, aD);

        // ---- combine2: h2(t) + out(t) (uses saved mv2h(t) partials) ----
        float h2n[MPT];
#pragma unroll
        for (int m = 0; m < MPT; m++) {
            float2 va = unpack2(aA[m]);
            float2 vb = unpack2(aB[m]);
            float za = va.x + va.y + z2A[m] + bp2.x;
            float zb = vb.x + vb.y + z2B[m] + bp2.y;
            float a1 = kA * __fdividef(1.0f, 1.0f + __expf(kmul * za)) + kB;
            float a2 = sigf(zb);
            float g_r = __shfl_xor_sync(0xffffffffu, a1, 1);
            float o_r = __shfl_xor_sync(0xffffffffu, a2, 1);
            c2[m]  = a2 * c2[m] + a1 * g_r;
            h2n[m] = o_r * tanhf_fast(c2[m]);
        }
        if (gs == 0 && j < HH) {
#pragma unroll
            for (int m = 0; m < MPT; m++)
                hd2[(e0 + m) * HROW + j] = h2n[m];
        }
#pragma unroll
        for (int m = 0; m < MPT; m++) {
            float p = wl * h2n[m];
#pragma unroll
            for (int off = 16; off > 0; off >>= 1)
                p += __shfl_xor_sync(0xffffffffu, p, off);
            if ((tid & 31) == 0) atomicAdd(&ovP[e0 + m], p);
        }
        __syncthreads();                                  // BAR-A: h2(t), out(t) final

        // out(t) -> gmem; reset out(t+1) slot; fetch x(t+1)
        if (tid < epc)
            out[(size_t)(b0 + tid) * TTOT + t] = ovP[tid];
        if (tid >= 128 && tid < 144) ovN[tid - 128] = blin_r;
        float xm[MPT];
        if (t + 1 < TSEQ) {
#pragma unroll
            for (int m = 0; m < MPT; m++) xm[m] = xs[(e0 + m) * TSEQ + (t + 1)];
        } else {
#pragma unroll
            for (int m = 0; m < MPT; m++) xm[m] = ovP[e0 + m];
        }

        // ---- phase B: mv2h(t+1) over h2(t); partials saved for next combine2 ----
#pragma unroll
        for (int m = 0; m < MPT; m++) { aA[m] = 0; aB[m] = 0; }
        matvec_acc(W2hr, hd2g, aA, aB);
#pragma unroll
        for (int m = 0; m < MPT; m++) {
            float2 va = unpack2(aA[m]); z2A[m] = va.x + va.y;
            float2 vb = unpack2(aB[m]); z2B[m] = vb.x + vb.y;
        }

        // ---- combine1: h1(t+1) from mv1(t+1) partials + x(t+1) ----
        float h1n[MPT];
#pragma unroll
        for (int m = 0; m < MPT; m++) {
            float2 vc = unpack2(aC[m]);
            float2 vd = unpack2(aD[m]);
            float za = vc.x + vc.y + fmaf(wxp.x, xm[m], bp1.x);
            float zb = vd.x + vd.y + fmaf(wxp.y, xm[m], bp1.y);
            float a1 = kA * __fdividef(1.0f, 1.0f + __expf(kmul * za)) + kB;
            float a2 = sigf(zb);
            float g_r = __shfl_xor_sync(0xffffffffu, a1, 1);
            float o_r = __shfl_xor_sync(0xffffffffu, a2, 1);
            c1[m]  = a2 * c1[m] + a1 * g_r;
            h1n[m] = o_r * tanhf_fast(c1[m]);
        }
        if (gs == 0 && j < HH) {
#pragma unroll
            for (int m = 0; m < MPT; m++)
                hd1[(e0 + m) * HROW + j] = h1n[m];
        }
        __syncthreads();                                  // BAR-B: h1(t+1) visible
    }
}

extern "C" void kernel_launch(void* const* d_in, const int* in_sizes, int n_in,
                              void* d_out, int out_size) {
    const float* input = (const float*)d_in[0];
    const float* Wih1  = (const float*)d_in[1];
    const float* Whh1  = (const float*)d_in[2];
    const float* bih1  = (const float*)d_in[3];
    const float* bhh1  = (const float*)d_in[4];
    const float* Wih2  = (const float*)d_in[5];
    const float* Whh2  = (const float*)d_in[6];
    const float* bih2  = (const float*)d_in[7];
    const float* bhh2  = (const float*)d_in[8];
    const float* Wlin  = (const float*)d_in[9];
    const float* blin  = (const float*)d_in[10];
    // d_in[11] = "future" (=32), baked in as a constant.

    cudaFuncSetAttribute(lstm_seq_kernel,
                         cudaFuncAttributeMaxDynamicSharedMemorySize, SM_BYTES);
    lstm_seq_kernel<<<NCTA, NTHR, SM_BYTES>>>(input, Wih1, Whh1, bih1, bhh1,
                                              Wih2, Whh2, bih2, bhh2,
                                              Wlin, blin, (float*)d_out);
}